// round 6
// baseline (speedup 1.0000x reference)
#include <cuda_runtime.h>
#include <cuda_fp16.h>
#include <math.h>

#define Tsz 512
#define FS 64
#define FC 32
#define H 256
#define LN_EPS 1e-5f

typedef unsigned long long ull;

// fp16 weights, k-major, pair-packed {m1[k,j], m2[k,j]} as one half2 per k-row.
// One uint4 = 4 consecutive k-rows. gh[r4*H + j].
__device__ uint4 gh_s0[(FS / 4) * H];   // {Win0_seq, Wg0_seq}
__device__ uint4 gh_c0[(FC / 4) * H];   // {Win0_ctx, Wg0_ctx}
__device__ uint4 gh_h0[(H / 4) * H];    // {Wg0_h,    Wrec0}
__device__ uint4 gh_x1[(H / 4) * H];    // {Win1,     Wg1_x}
__device__ uint4 gh_h1[(H / 4) * H];    // {Wg1_h,    Wrec1}

__device__ __forceinline__ unsigned pack_h2(float a, float b) {
    __half2 h = __floats2half2_rn(a, b);   // a -> lo lane, b -> hi lane
    return *reinterpret_cast<unsigned*>(&h);
}

__global__ void setup_kernel(const float* __restrict__ Win0,
                             const float* __restrict__ Wrec0,
                             const float* __restrict__ Wg0,
                             const float* __restrict__ Win1,
                             const float* __restrict__ Wrec1,
                             const float* __restrict__ Wg1) {
    int j = threadIdx.x;
    int r = blockIdx.x;   // 0..215 across all regions (4 k-rows each)
    uint4 u;
    if (r < 16) {                       // s0: rows 4r..4r+3
        int k = 4 * r;
        u.x = pack_h2(Win0[j * 96 + k + 0], Wg0[j * 352 + k + 0]);
        u.y = pack_h2(Win0[j * 96 + k + 1], Wg0[j * 352 + k + 1]);
        u.z = pack_h2(Win0[j * 96 + k + 2], Wg0[j * 352 + k + 2]);
        u.w = pack_h2(Win0[j * 96 + k + 3], Wg0[j * 352 + k + 3]);
        gh_s0[r * H + j] = u;
    } else if (r < 24) {                // c0
        int kk = 4 * (r - 16);
        u.x = pack_h2(Win0[j * 96 + 64 + kk + 0], Wg0[j * 352 + 64 + kk + 0]);
        u.y = pack_h2(Win0[j * 96 + 64 + kk + 1], Wg0[j * 352 + 64 + kk + 1]);
        u.z = pack_h2(Win0[j * 96 + 64 + kk + 2], Wg0[j * 352 + 64 + kk + 2]);
        u.w = pack_h2(Win0[j * 96 + 64 + kk + 3], Wg0[j * 352 + 64 + kk + 3]);
        gh_c0[(r - 16) * H + j] = u;
    } else if (r < 88) {                // h0
        int kk = 4 * (r - 24);
        u.x = pack_h2(Wg0[j * 352 + 96 + kk + 0], Wrec0[j * H + kk + 0]);
        u.y = pack_h2(Wg0[j * 352 + 96 + kk + 1], Wrec0[j * H + kk + 1]);
        u.z = pack_h2(Wg0[j * 352 + 96 + kk + 2], Wrec0[j * H + kk + 2]);
        u.w = pack_h2(Wg0[j * 352 + 96 + kk + 3], Wrec0[j * H + kk + 3]);
        gh_h0[(r - 24) * H + j] = u;
    } else if (r < 152) {               // x1
        int kk = 4 * (r - 88);
        u.x = pack_h2(Win1[j * H + kk + 0], Wg1[j * 512 + kk + 0]);
        u.y = pack_h2(Win1[j * H + kk + 1], Wg1[j * 512 + kk + 1]);
        u.z = pack_h2(Win1[j * H + kk + 2], Wg1[j * 512 + kk + 2]);
        u.w = pack_h2(Win1[j * H + kk + 3], Wg1[j * 512 + kk + 3]);
        gh_x1[(r - 88) * H + j] = u;
    } else {                            // h1
        int kk = 4 * (r - 152);
        u.x = pack_h2(Wg1[j * 512 + 256 + kk + 0], Wrec1[j * H + kk + 0]);
        u.y = pack_h2(Wg1[j * 512 + 256 + kk + 1], Wrec1[j * H + kk + 1]);
        u.z = pack_h2(Wg1[j * 512 + 256 + kk + 2], Wrec1[j * H + kk + 2]);
        u.w = pack_h2(Wg1[j * 512 + 256 + kk + 3], Wrec1[j * H + kk + 3]);
        gh_h1[(r - 152) * H + j] = u;
    }
}

// ---- packed fp32x2 helpers ----
__device__ __forceinline__ ull pk2(float a, float b) {
    ull r; asm("mov.b64 %0,{%1,%2};" : "=l"(r) : "f"(a), "f"(b)); return r;
}
__device__ __forceinline__ void up2(ull v, float& a, float& b) {
    asm("mov.b64 {%0,%1},%2;" : "=f"(a), "=f"(b) : "l"(v));
}
__device__ __forceinline__ void fma2(ull& d, ull a, ull b) {
    asm("fma.rn.f32x2 %0,%1,%2,%0;" : "+l"(d) : "l"(a), "l"(b));
}
__device__ __forceinline__ ull add2(ull a, ull b) {
    ull r; asm("add.rn.f32x2 %0,%1,%2;" : "=l"(r) : "l"(a), "l"(b)); return r;
}
// half2 -> {f32(lo), f32(hi)} packed 64-bit (ready as FMA2 multiplier)
__device__ __forceinline__ ull h2f2(unsigned h) {
    ull r;
    asm("{\n\t.reg .b16 lo,hi;\n\t.reg .f32 flo,fhi;\n\t"
        "mov.b32 {lo,hi},%1;\n\t"
        "cvt.f32.f16 flo,lo;\n\tcvt.f32.f16 fhi,hi;\n\t"
        "mov.b64 %0,{flo,fhi};\n\t}" : "=l"(r) : "r"(h));
    return r;
}

// ---- fast transcendentals (abs err ~1e-7; threshold 1e-3) ----
__device__ __forceinline__ float fast_tanh(float x) {
    float xc = fminf(fmaxf(x, -15.f), 15.f);
    float e  = __expf(2.f * xc);
    return __fdividef(e - 1.f, e + 1.f);
}
__device__ __forceinline__ float fast_sigmoid(float x) {
    return __fdividef(1.f, 1.f + __expf(-x));
}

// ---- hh stored PRE-DUPLICATED: hhd[4*k + b] = {h_b, h_b} ----
__device__ __forceinline__ void st_dup4(ull* dst, float a, float b, float c, float d) {
    *(ulonglong2*)(dst)     = make_ulonglong2(pk2(a, a), pk2(b, b));
    *(ulonglong2*)(dst + 2) = make_ulonglong2(pk2(c, c), pk2(d, d));
}

// acc[b] lanes = {matrix1_acc, matrix2_acc} for batch b.
__device__ __forceinline__ void comp4(uint4 w, const ull* __restrict__ hhd,
                                      int k0, ull acc[4]) {
#pragma unroll
    for (int i = 0; i < 4; i++) {
        ull wp = h2f2((&w.x)[i]);                                   // {m1, m2} fp32
        ulonglong2 hA = *(const ulonglong2*)(hhd + 4 * (size_t)(k0 + i));     // {h0,h0},{h1,h1}
        ulonglong2 hB = *(const ulonglong2*)(hhd + 4 * (size_t)(k0 + i) + 2); // {h2,h2},{h3,h3}
        fma2(acc[0], wp, hA.x); fma2(acc[1], wp, hA.y);
        fma2(acc[2], wp, hB.x); fma2(acc[3], wp, hB.y);
    }
}

// 16-k-row block: 4x LDG.128 preload / compute
__device__ __forceinline__ void pre4(uint4 w[4], const uint4* __restrict__ g,
                                     int r4, int j) {
#pragma unroll
    for (int i = 0; i < 4; i++) w[i] = g[(size_t)(r4 + i) * H + j];
}
__device__ __forceinline__ void comp16(const uint4 w[4], const ull* __restrict__ hhd,
                                       int k0, ull acc[4]) {
#pragma unroll
    for (int i = 0; i < 4; i++) comp4(w[i], hhd, k0 + 4 * i, acc);
}

// Pipelined matvec over NB 16-row blocks starting at 4-row index r4base.
// wA must hold block 0 on entry (preloaded behind a barrier).
template<int NB>
__device__ __forceinline__ void matvecS(const uint4* __restrict__ g, int j,
                                        int r4base, const ull* __restrict__ hhd,
                                        uint4 wA[4], ull acc[4]) {
    uint4 wB[4];
#pragma unroll 1
    for (int b = 0; b < NB; b += 2) {
        pre4(wB, g, r4base + (b + 1) * 4, j);
        comp16(wA, hhd, (r4base + b * 4) * 4, acc);
        if (b + 2 < NB) pre4(wA, g, r4base + (b + 2) * 4, j);
        comp16(wB, hhd, (r4base + (b + 1) * 4) * 4, acc);
    }
}

// Block-wide sum of 8 per-thread floats over 512 threads (16 warps).
__device__ __forceinline__ void block_reduce8(float v[8], float* red,
                                              int lane, int warp, float out[8]) {
#pragma unroll
    for (int off = 16; off > 0; off >>= 1) {
#pragma unroll
        for (int i = 0; i < 8; i++)
            v[i] += __shfl_xor_sync(0xffffffffu, v[i], off);
    }
    if (lane == 0) {
#pragma unroll
        for (int i = 0; i < 8; i++) red[warp * 8 + i] = v[i];
    }
    __syncthreads();
#pragma unroll
    for (int i = 0; i < 8; i++) out[i] = 0.f;
#pragma unroll
    for (int w = 0; w < 16; w++) {
#pragma unroll
        for (int i = 0; i < 8; i++) out[i] += red[w * 8 + i];
    }
    __syncthreads();
}

// RK4 + LayerNorm + tanh, k-split across two thread-halves.
// Entry: hh2[0] holds current h duplicated (written by half 0), wA holds g blk 0.
// Exit: h updated (half 0 only), wA holds gnext block 0.
__device__ __forceinline__ void rk4_ln(const uint4* __restrict__ g, int r4base,
                                       const uint4* __restrict__ gnext, int r4next,
                                       ull (*hh2)[4 * H], ull (*part)[256], float* red,
                                       int jj, int half, int lane, int warp,
                                       float h[4], const float pin[4], const float pg[4],
                                       float invtau, float lng, float lnb,
                                       uint4 wA[4]) {
    float hs[4], kacc[4], hn[4];
#pragma unroll
    for (int b = 0; b < 4; b++) hs[b] = h[b];

#pragma unroll 1
    for (int s = 0; s < 4; s++) {
        __syncthreads();   // syncA: hh2[s&1] + wA ready
        ull acc[4];
        if (half == 0) {
#pragma unroll
            for (int b = 0; b < 4; b++) acc[b] = pk2(pg[b], 0.f);  // {gate, rec}
        } else {
#pragma unroll
            for (int b = 0; b < 4; b++) acc[b] = 0ull;
        }
        matvecS<8>(g, jj, r4base, hh2[s & 1], wA, acc);
        if (half == 1) {
#pragma unroll
            for (int b = 0; b < 4; b++) part[b][jj] = acc[b];
        }
        __syncthreads();   // syncB: partials visible
        if (s < 3) pre4(wA, g, r4base, jj);
        else       pre4(wA, gnext, r4next, jj);
        if (half == 0) {
            float ag[4], ar[4];
#pragma unroll
            for (int b = 0; b < 4; b++) {
                acc[b] = add2(acc[b], part[b][jj]);
                up2(acc[b], ag[b], ar[b]);
            }
            float cn  = (s < 2) ? 0.5f : 1.0f;
            float wks = (s == 1 || s == 2) ? 2.0f : 1.0f;
#pragma unroll
            for (int b = 0; b < 4; b++) {
                float tg = fast_tanh(ag[b]);
                float gg = fast_sigmoid(tg);
                float kb = pin[b] - hs[b] * invtau + gg * ar[b];
                if (s == 0) kacc[b] = kb; else kacc[b] += wks * kb;
                if (s < 3) hs[b] = h[b] + cn * kb;
            }
            if (s < 3)
                st_dup4(&hh2[(s + 1) & 1][4 * jj], hs[0], hs[1], hs[2], hs[3]);
        }
    }

    float v8[8];
    if (half == 0) {
#pragma unroll
        for (int b = 0; b < 4; b++) {
            hn[b]     = h[b] + kacc[b] * (1.f / 6.f);
            v8[b]     = hn[b];
            v8[4 + b] = hn[b] * hn[b];
        }
    } else {
#pragma unroll
        for (int i = 0; i < 8; i++) v8[i] = 0.f;
    }
    float o8[8];
    block_reduce8(v8, red, lane, warp, o8);
    if (half == 0) {
#pragma unroll
        for (int b = 0; b < 4; b++) {
            float mu   = o8[b] * (1.f / (float)H);
            float var  = o8[4 + b] * (1.f / (float)H) - mu * mu;
            float rstd = rsqrtf(var + LN_EPS);
            h[b] = fast_tanh((hn[b] - mu) * rstd * lng + lnb);   // clip is a no-op
        }
    }
}

__global__ __launch_bounds__(512, 1)
void ltc_main(const float* __restrict__ seq,  const float* __restrict__ ctx,
              const float* __restrict__ tau0, const float* __restrict__ bg0,
              const float* __restrict__ lng0, const float* __restrict__ lnb0,
              const float* __restrict__ tau1, const float* __restrict__ bg1,
              const float* __restrict__ lng1, const float* __restrict__ lnb1,
              const float* __restrict__ cW1,  const float* __restrict__ cb1,
              const float* __restrict__ cW2,  const float* __restrict__ cb2,
              float* __restrict__ out) {
    __shared__ __align__(16) ull hh2[2][4 * H];   // stage vector, DUPLICATED pairs
    __shared__ __align__(16) ull xind[4 * H];     // layer-1 input, duplicated
    __shared__ __align__(16) ull xsd[4 * FS];     // seq features (ctx at init), dup
    __shared__ __align__(16) ull part[4][256];    // cross-half partials {m1,m2}
    __shared__ __align__(16) ull cwg[4][256];     // ctx-folded {cwin_b, cg_b}
    __shared__ float red[128];

    int tid  = threadIdx.x;
    int jj   = tid & 255;          // neuron
    int half = tid >> 8;           // k-half
    int lane = tid & 31, warp = tid >> 5;
    int b0   = blockIdx.x * 4;

    float invt0 = 1.f / (log1pf(expf(tau0[jj])) + 1.f);
    float invt1 = 1.f / (log1pf(expf(tau1[jj])) + 1.f);
    float lng0v = lng0[jj], lnb0v = lnb0[jj];
    float lng1v = lng1[jj], lnb1v = lnb1[jj];
    float rbg1  = bg1[jj];

    // ---- ctx contributions to layer-0 pre-activations (constant over t) ----
    if (tid < FC) {
        float c0 = ctx[(b0 + 0) * FC + tid], c1 = ctx[(b0 + 1) * FC + tid];
        float c2 = ctx[(b0 + 2) * FC + tid], c3 = ctx[(b0 + 3) * FC + tid];
        st_dup4(&xsd[4 * tid], c0, c1, c2, c3);
    }
    __syncthreads();
    if (half == 0) {
        ull acc[4];
        float bv = bg0[jj];
#pragma unroll
        for (int b = 0; b < 4; b++) acc[b] = pk2(0.f, bv);   // {cwin, cg}
#pragma unroll
        for (int r4 = 0; r4 < FC / 4; r4++) {
            uint4 w = gh_c0[r4 * H + jj];
            comp4(w, xsd, 4 * r4, acc);
        }
#pragma unroll
        for (int b = 0; b < 4; b++) cwg[b][jj] = acc[b];
    }
    __syncthreads();

    float h0r[4] = {0.f, 0.f, 0.f, 0.f};
    float h1r[4] = {0.f, 0.f, 0.f, 0.f};

    const int r4S = half * 8;    // proj0: FS=64 rows -> 16 r4; half = 8
    const int r4H = half * 32;   // H matvecs: 256 rows -> 64 r4; half = 32

    uint4 wA[4];
    pre4(wA, gh_s0, r4S, jj);

#pragma unroll 1
    for (int t = 0; t < Tsz; t++) {
        if (tid < FS) {
            size_t o = (size_t)t * FS + tid;
            float s0v = seq[(size_t)(b0 + 0) * Tsz * FS + o];
            float s1v = seq[(size_t)(b0 + 1) * Tsz * FS + o];
            float s2v = seq[(size_t)(b0 + 2) * Tsz * FS + o];
            float s3v = seq[(size_t)(b0 + 3) * Tsz * FS + o];
            st_dup4(&xsd[4 * tid], s0v, s1v, s2v, s3v);
        }
        __syncthreads();   // syncA for proj0 (xsd + wA ready)

        // ---- layer 0 input projection; acc lanes = {pin, pg} ----
        ull acc[4];
        if (half == 0) {
#pragma unroll
            for (int b = 0; b < 4; b++) acc[b] = cwg[b][jj];
        } else {
#pragma unroll
            for (int b = 0; b < 4; b++) acc[b] = 0ull;
        }
        matvecS<2>(gh_s0, jj, r4S, xsd, wA, acc);
        if (half == 1) {
#pragma unroll
            for (int b = 0; b < 4; b++) part[b][jj] = acc[b];
        }
        __syncthreads();   // syncB
        pre4(wA, gh_h0, r4H, jj);
        float pin[4], pg[4];
        if (half == 0) {
#pragma unroll
            for (int b = 0; b < 4; b++) {
                acc[b] = add2(acc[b], part[b][jj]);
                up2(acc[b], pin[b], pg[b]);
            }
            st_dup4(&hh2[0][4 * jj], h0r[0], h0r[1], h0r[2], h0r[3]);
        }
        rk4_ln(gh_h0, r4H, gh_x1, r4H, hh2, part, red, jj, half, lane, warp,
               h0r, pin, pg, invt0, lng0v, lnb0v, wA);

        // ---- hand layer-0 output to layer 1 ----
        if (half == 0)
            st_dup4(&xind[4 * jj], h0r[0], h0r[1], h0r[2], h0r[3]);
        __syncthreads();   // syncA for proj1 (xind + wA=gh_x1 blk0 ready)

        // ---- layer 1 input projection ----
        if (half == 0) {
#pragma unroll
            for (int b = 0; b < 4; b++) acc[b] = pk2(0.f, rbg1);
        } else {
#pragma unroll
            for (int b = 0; b < 4; b++) acc[b] = 0ull;
        }
        matvecS<8>(gh_x1, jj, r4H, xind, wA, acc);
        if (half == 1) {
#pragma unroll
            for (int b = 0; b < 4; b++) part[b][jj] = acc[b];
        }
        __syncthreads();   // syncB
        pre4(wA, gh_h1, r4H, jj);
        if (half == 0) {
#pragma unroll
            for (int b = 0; b < 4; b++) {
                acc[b] = add2(acc[b], part[b][jj]);
                up2(acc[b], pin[b], pg[b]);
            }
            st_dup4(&hh2[0][4 * jj], h1r[0], h1r[1], h1r[2], h1r[3]);
        }
        rk4_ln(gh_h1, r4H, gh_s0, r4S, hh2, part, red, jj, half, lane, warp,
               h1r, pin, pg, invt1, lng1v, lnb1v, wA);
    }

    // ---- head: out = relu(h1 @ cW1.T + cb1) @ cW2.T + cb2 ----
    if (half == 0)
        st_dup4(&xind[4 * jj], h1r[0], h1r[1], h1r[2], h1r[3]);
    __syncthreads();

    float p[4] = {0.f, 0.f, 0.f, 0.f};
    if (tid < 128) {
        float acc[4];
        float bb = cb1[tid];
#pragma unroll
        for (int b = 0; b < 4; b++) acc[b] = bb;
        const float* xf = (const float*)xind;   // dup pairs: x_b = xf[8*k + 2*b]
#pragma unroll 8
        for (int k = 0; k < H; k++) {
            float w = cW1[tid * H + k];
            acc[0] += w * xf[8 * k + 0];
            acc[1] += w * xf[8 * k + 2];
            acc[2] += w * xf[8 * k + 4];
            acc[3] += w * xf[8 * k + 6];
        }
        float w2 = cW2[tid];
#pragma unroll
        for (int b = 0; b < 4; b++) p[b] = fmaxf(acc[b], 0.f) * w2;
    }
    float v8[8], o8[8];
#pragma unroll
    for (int i = 0; i < 8; i++) v8[i] = (i < 4) ? p[i] : 0.f;
    block_reduce8(v8, red, lane, warp, o8);
    if (tid < 4) out[b0 + tid] = o8[tid] + cb2[0];
}

extern "C" void kernel_launch(void* const* d_in, const int* in_sizes, int n_in,
                              void* d_out, int out_size) {
    const float* seq   = (const float*)d_in[0];
    const float* ctx   = (const float*)d_in[1];
    const float* tau0  = (const float*)d_in[2];
    const float* Win0  = (const float*)d_in[3];
    const float* Wrec0 = (const float*)d_in[4];
    const float* Wg0   = (const float*)d_in[5];
    const float* bg0   = (const float*)d_in[6];
    const float* lng0  = (const float*)d_in[7];
    const float* lnb0  = (const float*)d_in[8];
    const float* tau1  = (const float*)d_in[9];
    const float* Win1  = (const float*)d_in[10];
    const float* Wrec1 = (const float*)d_in[11];
    const float* Wg1   = (const float*)d_in[12];
    const float* bg1   = (const float*)d_in[13];
    const float* lng1  = (const float*)d_in[14];
    const float* lnb1  = (const float*)d_in[15];
    const float* cW1   = (const float*)d_in[16];
    const float* cb1   = (const float*)d_in[17];
    const float* cW2   = (const float*)d_in[18];
    const float* cb2   = (const float*)d_in[19];
    float* out = (float*)d_out;

    setup_kernel<<<216, 256>>>(Win0, Wrec0, Wg0, Win1, Wrec1, Wg1);
    ltc_main<<<128, 512>>>(seq, ctx, tau0, bg0, lng0, lnb0,
                           tau1, bg1, lng1, lnb1,
                           cW1, cb1, cW2, cb2, out);
}

// round 8
// speedup vs baseline: 1.2721x; 1.2721x over previous
#include <cuda_runtime.h>
#include <cuda_fp16.h>
#include <math.h>

#define Tsz 512
#define FS 64
#define FC 32
#define H 256
#define LN_EPS 1e-5f

typedef unsigned long long ull;

// fp16 weights, k-major, pair-packed {m1[k,j], m2[k,j]} as one half2 per k-row.
// One uint4 = 4 consecutive k-rows. gh[r4*H + j].
__device__ uint4 gh_s0[(FS / 4) * H];   // {Win0_seq, Wg0_seq}
__device__ uint4 gh_c0[(FC / 4) * H];   // {Win0_ctx, Wg0_ctx}
__device__ uint4 gh_h0[(H / 4) * H];    // {Wg0_h,    Wrec0}
__device__ uint4 gh_x1[(H / 4) * H];    // {Win1,     Wg1_x}
__device__ uint4 gh_h1[(H / 4) * H];    // {Wg1_h,    Wrec1}

__device__ __forceinline__ unsigned pack_h2(float a, float b) {
    __half2 h = __floats2half2_rn(a, b);   // a -> lo lane, b -> hi lane
    return *reinterpret_cast<unsigned*>(&h);
}

__global__ void setup_kernel(const float* __restrict__ Win0,
                             const float* __restrict__ Wrec0,
                             const float* __restrict__ Wg0,
                             const float* __restrict__ Win1,
                             const float* __restrict__ Wrec1,
                             const float* __restrict__ Wg1) {
    int j = threadIdx.x;
    int r = blockIdx.x;   // 0..215 across all regions (4 k-rows each)
    uint4 u;
    if (r < 16) {                       // s0
        int k = 4 * r;
        u.x = pack_h2(Win0[j * 96 + k + 0], Wg0[j * 352 + k + 0]);
        u.y = pack_h2(Win0[j * 96 + k + 1], Wg0[j * 352 + k + 1]);
        u.z = pack_h2(Win0[j * 96 + k + 2], Wg0[j * 352 + k + 2]);
        u.w = pack_h2(Win0[j * 96 + k + 3], Wg0[j * 352 + k + 3]);
        gh_s0[r * H + j] = u;
    } else if (r < 24) {                // c0
        int kk = 4 * (r - 16);
        u.x = pack_h2(Win0[j * 96 + 64 + kk + 0], Wg0[j * 352 + 64 + kk + 0]);
        u.y = pack_h2(Win0[j * 96 + 64 + kk + 1], Wg0[j * 352 + 64 + kk + 1]);
        u.z = pack_h2(Win0[j * 96 + 64 + kk + 2], Wg0[j * 352 + 64 + kk + 2]);
        u.w = pack_h2(Win0[j * 96 + 64 + kk + 3], Wg0[j * 352 + 64 + kk + 3]);
        gh_c0[(r - 16) * H + j] = u;
    } else if (r < 88) {                // h0
        int kk = 4 * (r - 24);
        u.x = pack_h2(Wg0[j * 352 + 96 + kk + 0], Wrec0[j * H + kk + 0]);
        u.y = pack_h2(Wg0[j * 352 + 96 + kk + 1], Wrec0[j * H + kk + 1]);
        u.z = pack_h2(Wg0[j * 352 + 96 + kk + 2], Wrec0[j * H + kk + 2]);
        u.w = pack_h2(Wg0[j * 352 + 96 + kk + 3], Wrec0[j * H + kk + 3]);
        gh_h0[(r - 24) * H + j] = u;
    } else if (r < 152) {               // x1
        int kk = 4 * (r - 88);
        u.x = pack_h2(Win1[j * H + kk + 0], Wg1[j * 512 + kk + 0]);
        u.y = pack_h2(Win1[j * H + kk + 1], Wg1[j * 512 + kk + 1]);
        u.z = pack_h2(Win1[j * H + kk + 2], Wg1[j * 512 + kk + 2]);
        u.w = pack_h2(Win1[j * H + kk + 3], Wg1[j * 512 + kk + 3]);
        gh_x1[(r - 88) * H + j] = u;
    } else {                            // h1
        int kk = 4 * (r - 152);
        u.x = pack_h2(Wg1[j * 512 + 256 + kk + 0], Wrec1[j * H + kk + 0]);
        u.y = pack_h2(Wg1[j * 512 + 256 + kk + 1], Wrec1[j * H + kk + 1]);
        u.z = pack_h2(Wg1[j * 512 + 256 + kk + 2], Wrec1[j * H + kk + 2]);
        u.w = pack_h2(Wg1[j * 512 + 256 + kk + 3], Wrec1[j * H + kk + 3]);
        gh_h1[(r - 152) * H + j] = u;
    }
}

// ---- packed fp32x2 helpers ----
__device__ __forceinline__ ull pk2(float a, float b) {
    ull r; asm("mov.b64 %0,{%1,%2};" : "=l"(r) : "f"(a), "f"(b)); return r;
}
__device__ __forceinline__ void up2(ull v, float& a, float& b) {
    asm("mov.b64 {%0,%1},%2;" : "=f"(a), "=f"(b) : "l"(v));
}
__device__ __forceinline__ void fma2(ull& d, ull a, ull b) {
    asm("fma.rn.f32x2 %0,%1,%2,%0;" : "+l"(d) : "l"(a), "l"(b));
}
__device__ __forceinline__ ull add2(ull a, ull b) {
    ull r; asm("add.rn.f32x2 %0,%1,%2;" : "=l"(r) : "l"(a), "l"(b)); return r;
}
// half2 {m1,m2} -> two DUPLICATED fp32 pairs {m1,m1}, {m2,m2} (register side)
__device__ __forceinline__ void h2dup(unsigned h, ull& w1, ull& w2) {
    asm("{\n\t.reg .b16 lo,hi;\n\t.reg .f32 f1,f2;\n\t"
        "mov.b32 {lo,hi},%2;\n\t"
        "cvt.f32.f16 f1,lo;\n\tcvt.f32.f16 f2,hi;\n\t"
        "mov.b64 %0,{f1,f1};\n\tmov.b64 %1,{f2,f2};\n\t}"
        : "=l"(w1), "=l"(w2) : "r"(h));
}

// ---- fast transcendentals (abs err ~1e-7; threshold 1e-3) ----
__device__ __forceinline__ float fast_tanh(float x) {
    float xc = fminf(fmaxf(x, -15.f), 15.f);
    float e  = __expf(2.f * xc);
    return __fdividef(e - 1.f, e + 1.f);
}
__device__ __forceinline__ float fast_sigmoid(float x) {
    return __fdividef(1.f, 1.f + __expf(-x));
}

// ---- hh stored batch-paired: hhp[2*k] = {h0,h1}, hhp[2*k+1] = {h2,h3} ----
__device__ __forceinline__ void st_pair4(ull* dst, float a, float b, float c, float d) {
    *(ulonglong2*)dst = make_ulonglong2(pk2(a, b), pk2(c, d));
}

// acc: a1_* = matrix1 (batch pairs 01/23), a2_* = matrix2.
__device__ __forceinline__ void comp4(uint4 w, const ull* __restrict__ hhp,
                                      int k0,
                                      ull& a1_01, ull& a1_23, ull& a2_01, ull& a2_23) {
#pragma unroll
    for (int i = 0; i < 4; i++) {
        ull w1d, w2d;
        h2dup((&w.x)[i], w1d, w2d);
        ulonglong2 h = *(const ulonglong2*)(hhp + 2 * (size_t)(k0 + i));  // 1 LDS.128
        fma2(a1_01, w1d, h.x); fma2(a1_23, w1d, h.y);
        fma2(a2_01, w2d, h.x); fma2(a2_23, w2d, h.y);
    }
}

// 16-k-row block: 4x LDG.128 preload / compute
__device__ __forceinline__ void pre4(uint4 w[4], const uint4* __restrict__ g,
                                     int r4, int j) {
#pragma unroll
    for (int i = 0; i < 4; i++) w[i] = g[(size_t)(r4 + i) * H + j];
}
__device__ __forceinline__ void comp16(const uint4 w[4], const ull* __restrict__ hhp,
                                       int k0,
                                       ull& a1_01, ull& a1_23, ull& a2_01, ull& a2_23) {
#pragma unroll
    for (int i = 0; i < 4; i++) comp4(w[i], hhp, k0 + 4 * i, a1_01, a1_23, a2_01, a2_23);
}

// Pipelined matvec over NB 16-row blocks starting at 4-row index r4base.
// wA must hold block 0 on entry (preloaded behind a barrier).
template<int NB>
__device__ __forceinline__ void matvecS(const uint4* __restrict__ g, int j,
                                        int r4base, const ull* __restrict__ hhp,
                                        uint4 wA[4],
                                        ull& a1_01, ull& a1_23, ull& a2_01, ull& a2_23) {
    uint4 wB[4];
#pragma unroll 1
    for (int b = 0; b < NB; b += 2) {
        pre4(wB, g, r4base + (b + 1) * 4, j);
        comp16(wA, hhp, (r4base + b * 4) * 4, a1_01, a1_23, a2_01, a2_23);
        if (b + 2 < NB) pre4(wA, g, r4base + (b + 2) * 4, j);
        comp16(wB, hhp, (r4base + (b + 1) * 4) * 4, a1_01, a1_23, a2_01, a2_23);
    }
}

// Block-wide sum of 8 per-thread floats over 512 threads (16 warps).
__device__ __forceinline__ void block_reduce8(float v[8], float* red,
                                              int lane, int warp, float out[8]) {
#pragma unroll
    for (int off = 16; off > 0; off >>= 1) {
#pragma unroll
        for (int i = 0; i < 8; i++)
            v[i] += __shfl_xor_sync(0xffffffffu, v[i], off);
    }
    if (lane == 0) {
#pragma unroll
        for (int i = 0; i < 8; i++) red[warp * 8 + i] = v[i];
    }
    __syncthreads();
#pragma unroll
    for (int i = 0; i < 8; i++) out[i] = 0.f;
#pragma unroll
    for (int w = 0; w < 16; w++) {
#pragma unroll
        for (int i = 0; i < 8; i++) out[i] += red[w * 8 + i];
    }
    __syncthreads();
}

// RK4 + LayerNorm + tanh, k-split across two thread-halves.
// Entry: hh2[0] holds current h (batch-paired, written by half 0), wA = g blk 0.
// Exit: h updated (half 0 only), wA holds gnext block 0.
__device__ __forceinline__ void rk4_ln(const uint4* __restrict__ g, int r4base,
                                       const uint4* __restrict__ gnext, int r4next,
                                       ull (*hh2)[2 * H], ull (*part)[256], float* red,
                                       int jj, int half, int lane, int warp,
                                       float h[4], const float pin[4], const float pg[4],
                                       float invtau, float lng, float lnb,
                                       uint4 wA[4]) {
    float hs[4], kacc[4], hn[4];
#pragma unroll
    for (int b = 0; b < 4; b++) hs[b] = h[b];

#pragma unroll 1
    for (int s = 0; s < 4; s++) {
        __syncthreads();   // syncA: hh2[s&1] + wA ready
        ull ag01, ag23, ar01 = 0ull, ar23 = 0ull;
        if (half == 0) { ag01 = pk2(pg[0], pg[1]); ag23 = pk2(pg[2], pg[3]); }
        else           { ag01 = 0ull;              ag23 = 0ull; }
        matvecS<8>(g, jj, r4base, hh2[s & 1], wA, ag01, ag23, ar01, ar23);
        if (half == 1) {
            part[0][jj] = ag01; part[1][jj] = ag23;
            part[2][jj] = ar01; part[3][jj] = ar23;
        }
        __syncthreads();   // syncB: partials visible
        if (s < 3) pre4(wA, g, r4base, jj);
        else       pre4(wA, gnext, r4next, jj);
        if (half == 0) {
            ag01 = add2(ag01, part[0][jj]); ag23 = add2(ag23, part[1][jj]);
            ar01 = add2(ar01, part[2][jj]); ar23 = add2(ar23, part[3][jj]);
            float ag[4], ar[4];
            up2(ag01, ag[0], ag[1]); up2(ag23, ag[2], ag[3]);
            up2(ar01, ar[0], ar[1]); up2(ar23, ar[2], ar[3]);
            float cn  = (s < 2) ? 0.5f : 1.0f;
            float wks = (s == 1 || s == 2) ? 2.0f : 1.0f;
#pragma unroll
            for (int b = 0; b < 4; b++) {
                float tg = fast_tanh(ag[b]);
                float gg = fast_sigmoid(tg);
                float kb = pin[b] - hs[b] * invtau + gg * ar[b];
                if (s == 0) kacc[b] = kb; else kacc[b] += wks * kb;
                if (s < 3) hs[b] = h[b] + cn * kb;
            }
            if (s < 3)
                st_pair4(&hh2[(s + 1) & 1][2 * jj], hs[0], hs[1], hs[2], hs[3]);
        }
    }

    float v8[8];
    if (half == 0) {
#pragma unroll
        for (int b = 0; b < 4; b++) {
            hn[b]     = h[b] + kacc[b] * (1.f / 6.f);
            v8[b]     = hn[b];
            v8[4 + b] = hn[b] * hn[b];
        }
    } else {
#pragma unroll
        for (int i = 0; i < 8; i++) v8[i] = 0.f;
    }
    float o8[8];
    block_reduce8(v8, red, lane, warp, o8);
    if (half == 0) {
#pragma unroll
        for (int b = 0; b < 4; b++) {
            float mu   = o8[b] * (1.f / (float)H);
            float var  = o8[4 + b] * (1.f / (float)H) - mu * mu;
            float rstd = rsqrtf(var + LN_EPS);
            h[b] = fast_tanh((hn[b] - mu) * rstd * lng + lnb);   // clip is a no-op
        }
    }
}

__global__ __launch_bounds__(512, 1)
void ltc_main(const float* __restrict__ seq,  const float* __restrict__ ctx,
              const float* __restrict__ tau0, const float* __restrict__ bg0,
              const float* __restrict__ lng0, const float* __restrict__ lnb0,
              const float* __restrict__ tau1, const float* __restrict__ bg1,
              const float* __restrict__ lng1, const float* __restrict__ lnb1,
              const float* __restrict__ cW1,  const float* __restrict__ cb1,
              const float* __restrict__ cW2,  const float* __restrict__ cb2,
              float* __restrict__ out) {
    __shared__ __align__(16) ull hh2[2][2 * H];   // stage vector, batch-paired
    __shared__ __align__(16) ull xinp[2 * H];     // layer-1 input, batch-paired
    __shared__ __align__(16) ull xsp[2 * FS];     // seq features (ctx at init)
    __shared__ __align__(16) ull part[4][256];    // cross-half partials
    __shared__ __align__(16) ull cwg[4][256];     // ctx-folded {cwin, cg} pairs
    __shared__ float red[128];

    int tid  = threadIdx.x;
    int jj   = tid & 255;          // neuron
    int half = tid >> 8;           // k-half
    int lane = tid & 31, warp = tid >> 5;
    int b0   = blockIdx.x * 4;

    float invt0 = 1.f / (log1pf(expf(tau0[jj])) + 1.f);
    float invt1 = 1.f / (log1pf(expf(tau1[jj])) + 1.f);
    float lng0v = lng0[jj], lnb0v = lnb0[jj];
    float lng1v = lng1[jj], lnb1v = lnb1[jj];
    float rbg1  = bg1[jj];

    // ---- ctx contributions to layer-0 pre-activations (constant over t) ----
    if (tid < FC) {
        float c0 = ctx[(b0 + 0) * FC + tid], c1 = ctx[(b0 + 1) * FC + tid];
        float c2 = ctx[(b0 + 2) * FC + tid], c3 = ctx[(b0 + 3) * FC + tid];
        st_pair4(&xsp[2 * tid], c0, c1, c2, c3);
    }
    __syncthreads();
    if (half == 0) {
        ull p01 = 0ull, p23 = 0ull;
        float bv = bg0[jj];
        ull g01 = pk2(bv, bv), g23 = g01;
#pragma unroll
        for (int r4 = 0; r4 < FC / 4; r4++) {
            uint4 w = gh_c0[r4 * H + jj];
            comp4(w, xsp, 4 * r4, p01, p23, g01, g23);
        }
        cwg[0][jj] = p01; cwg[1][jj] = p23;
        cwg[2][jj] = g01; cwg[3][jj] = g23;
    }
    __syncthreads();

    float h0r[4] = {0.f, 0.f, 0.f, 0.f};
    float h1r[4] = {0.f, 0.f, 0.f, 0.f};

    const int r4S = half * 8;    // proj0: FS=64 rows -> 16 r4; half = 8
    const int r4H = half * 32;   // H matvecs: 256 rows -> 64 r4; half = 32

    uint4 wA[4];
    pre4(wA, gh_s0, r4S, jj);

#pragma unroll 1
    for (int t = 0; t < Tsz; t++) {
        if (tid < FS) {
            size_t o = (size_t)t * FS + tid;
            float s0v = seq[(size_t)(b0 + 0) * Tsz * FS + o];
            float s1v = seq[(size_t)(b0 + 1) * Tsz * FS + o];
            float s2v = seq[(size_t)(b0 + 2) * Tsz * FS + o];
            float s3v = seq[(size_t)(b0 + 3) * Tsz * FS + o];
            st_pair4(&xsp[2 * tid], s0v, s1v, s2v, s3v);
        }
        __syncthreads();   // syncA for proj0 (xsp + wA ready)

        // ---- layer 0 input projection: acc1 = pin, acc2 = pg ----
        ull p01, p23, g01, g23;
        if (half == 0) { p01 = cwg[0][jj]; p23 = cwg[1][jj];
                         g01 = cwg[2][jj]; g23 = cwg[3][jj]; }
        else           { p01 = 0ull; p23 = 0ull; g01 = 0ull; g23 = 0ull; }
        matvecS<2>(gh_s0, jj, r4S, xsp, wA, p01, p23, g01, g23);
        if (half == 1) {
            part[0][jj] = p01; part[1][jj] = p23;
            part[2][jj] = g01; part[3][jj] = g23;
        }
        __syncthreads();   // syncB
        pre4(wA, gh_h0, r4H, jj);
        float pin[4], pg[4];
        if (half == 0) {
            p01 = add2(p01, part[0][jj]); p23 = add2(p23, part[1][jj]);
            g01 = add2(g01, part[2][jj]); g23 = add2(g23, part[3][jj]);
            up2(p01, pin[0], pin[1]); up2(p23, pin[2], pin[3]);
            up2(g01, pg[0],  pg[1]);  up2(g23, pg[2],  pg[3]);
            st_pair4(&hh2[0][2 * jj], h0r[0], h0r[1], h0r[2], h0r[3]);
        }
        rk4_ln(gh_h0, r4H, gh_x1, r4H, hh2, part, red, jj, half, lane, warp,
               h0r, pin, pg, invt0, lng0v, lnb0v, wA);

        // ---- hand layer-0 output to layer 1 ----
        if (half == 0)
            st_pair4(&xinp[2 * jj], h0r[0], h0r[1], h0r[2], h0r[3]);
        __syncthreads();   // syncA for proj1 (xinp + wA=gh_x1 blk0 ready)

        // ---- layer 1 input projection ----
        if (half == 0) { p01 = 0ull; p23 = 0ull;
                         g01 = pk2(rbg1, rbg1); g23 = g01; }
        else           { p01 = 0ull; p23 = 0ull; g01 = 0ull; g23 = 0ull; }
        matvecS<8>(gh_x1, jj, r4H, xinp, wA, p01, p23, g01, g23);
        if (half == 1) {
            part[0][jj] = p01; part[1][jj] = p23;
            part[2][jj] = g01; part[3][jj] = g23;
        }
        __syncthreads();   // syncB
        pre4(wA, gh_h1, r4H, jj);
        if (half == 0) {
            p01 = add2(p01, part[0][jj]); p23 = add2(p23, part[1][jj]);
            g01 = add2(g01, part[2][jj]); g23 = add2(g23, part[3][jj]);
            up2(p01, pin[0], pin[1]); up2(p23, pin[2], pin[3]);
            up2(g01, pg[0],  pg[1]);  up2(g23, pg[2],  pg[3]);
            st_pair4(&hh2[0][2 * jj], h1r[0], h1r[1], h1r[2], h1r[3]);
        }
        rk4_ln(gh_h1, r4H, gh_s0, r4S, hh2, part, red, jj, half, lane, warp,
               h1r, pin, pg, invt1, lng1v, lnb1v, wA);
    }

    // ---- head: out = relu(h1 @ cW1.T + cb1) @ cW2.T + cb2 ----
    if (half == 0)
        st_pair4(&xinp[2 * jj], h1r[0], h1r[1], h1r[2], h1r[3]);
    __syncthreads();

    float p[4] = {0.f, 0.f, 0.f, 0.f};
    if (tid < 128) {
        float acc[4];
        float bb = cb1[tid];
#pragma unroll
        for (int b = 0; b < 4; b++) acc[b] = bb;
        const float* xf = (const float*)xinp;   // batch-paired: x_b = xf[4*k + b]
#pragma unroll 8
        for (int k = 0; k < H; k++) {
            float w = cW1[tid * H + k];
            acc[0] += w * xf[4 * k + 0];
            acc[1] += w * xf[4 * k + 1];
            acc[2] += w * xf[4 * k + 2];
            acc[3] += w * xf[4 * k + 3];
        }
        float w2 = cW2[tid];
#pragma unroll
        for (int b = 0; b < 4; b++) p[b] = fmaxf(acc[b], 0.f) * w2;
    }
    float v8[8], o8[8];
#pragma unroll
    for (int i = 0; i < 8; i++) v8[i] = (i < 4) ? p[i] : 0.f;
    block_reduce8(v8, red, lane, warp, o8);
    if (tid < 4) out[b0 + tid] = o8[tid] + cb2[0];
}

extern "C" void kernel_launch(void* const* d_in, const int* in_sizes, int n_in,
                              void* d_out, int out_size) {
    const float* seq   = (const float*)d_in[0];
    const float* ctx   = (const float*)d_in[1];
    const float* tau0  = (const float*)d_in[2];
    const float* Win0  = (const float*)d_in[3];
    const float* Wrec0 = (const float*)d_in[4];
    const float* Wg0   = (const float*)d_in[5];
    const float* bg0   = (const float*)d_in[6];
    const float* lng0  = (const float*)d_in[7];
    const float* lnb0  = (const float*)d_in[8];
    const float* tau1  = (const float*)d_in[9];
    const float* Win1  = (const float*)d_in[10];
    const float* Wrec1 = (const float*)d_in[11];
    const float* Wg1   = (const float*)d_in[12];
    const float* bg1   = (const float*)d_in[13];
    const float* lng1  = (const float*)d_in[14];
    const float* lnb1  = (const float*)d_in[15];
    const float* cW1   = (const float*)d_in[16];
    const float* cb1   = (const float*)d_in[17];
    const float* cW2   = (const float*)d_in[18];
    const float* cb2   = (const float*)d_in[19];
    float* out = (float*)d_out;

    setup_kernel<<<216, 256>>>(Win0, Wrec0, Wg0, Win1, Wrec1, Wg1);
    ltc_main<<<128, 512>>>(seq, ctx, tau0, bg0, lng0, lnb0,
                           tau1, bg1, lng1, lnb1,
                           cW1, cb1, cW2, cb2, out);
}